// round 3
// baseline (speedup 1.0000x reference)
#include <cuda_runtime.h>
#include <math.h>
#include <cstdint>

// ---------------- problem constants ----------------------------------------
#define NB    8
#define Cc    256
#define HW    961
#define Mrows 7688
#define MP    7808          // padded M = 61*128
#define HID   512
#define OUTF  256

// ---------------- scratch (device globals; zero-initialized) ----------------
__device__ float g_S0  [NB * Cc];
__device__ float g_YhiT[Cc * MP];
__device__ float g_YloT[Cc * MP];
__device__ float g_W1hT[Cc * HID];
__device__ float g_W1lT[Cc * HID];
__device__ float g_W2hT[HID * OUTF];
__device__ float g_W2lT[HID * OUTF];
__device__ float g_H1T [HID * MP];
__device__ float g_S1T [HID * 16];
__device__ float g_H2T [OUTF * MP];

// ---------------- helpers ----------------------------------------------------
__device__ __forceinline__ uint32_t smem_u32(const void* p) {
    uint32_t a;
    asm("{ .reg .u64 t; cvta.to.shared.u64 t, %1; cvt.u32.u64 %0, t; }"
        : "=r"(a) : "l"(p));
    return a;
}

__device__ __forceinline__ float tf32_rna(float a) {
    uint32_t u;
    asm("cvt.rna.tf32.f32 %0, %1;" : "=r"(u) : "f"(a));
    return __uint_as_float(u);
}

__device__ __forceinline__ float dinv_of(int b) {
    int deg = (b == 0 || b == NB - 1) ? 963 : 964;
    return 1.0f / sqrtf((float)deg);
}

#define MMA_TF32(d, a, b) \
    asm volatile("mma.sync.aligned.m16n8k8.row.col.f32.tf32.tf32.f32 " \
                 "{%0,%1,%2,%3},{%4,%5,%6,%7},{%8,%9},{%0,%1,%2,%3};" \
                 : "+f"((d)[0]), "+f"((d)[1]), "+f"((d)[2]), "+f"((d)[3]) \
                 : "r"((a)[0]), "r"((a)[1]), "r"((a)[2]), "r"((a)[3]), \
                   "r"((b)[0]), "r"((b)[1]))

#define CP_ASYNC16(dst32, src) \
    asm volatile("cp.async.cg.shared.global [%0], [%1], 16;" :: "r"(dst32), "l"(src))
#define CP_COMMIT()  asm volatile("cp.async.commit_group;" ::: "memory")
#define CP_WAIT1()   asm volatile("cp.async.wait_group 1;" ::: "memory")

// ---------------- small kernels ----------------------------------------------
__global__ void sum_x_kernel(const float* __restrict__ x, float* __restrict__ S0) {
    int bc = blockIdx.x;
    const float* src = x + (size_t)bc * HW;
    float s = 0.f;
    for (int p = threadIdx.x; p < HW; p += 256) s += src[p];
    __shared__ float red[8];
    #pragma unroll
    for (int off = 16; off; off >>= 1) s += __shfl_down_sync(0xffffffffu, s, off);
    if ((threadIdx.x & 31) == 0) red[threadIdx.x >> 5] = s;
    __syncthreads();
    if (threadIdx.x < 8) {
        s = red[threadIdx.x];
        #pragma unroll
        for (int off = 4; off; off >>= 1) s += __shfl_down_sync(0xffu, s, off);
        if (threadIdx.x == 0) S0[bc] = s;
    }
}

// transpose + tf32 split: W[Nr][Kc] row-major -> WhT/WlT [Kc][Nr]
__global__ void wsplit_t(const float* __restrict__ W,
                         float* __restrict__ WhT, float* __restrict__ WlT,
                         int Nr, int Kc) {
    __shared__ float t[32][33];
    int n0 = blockIdx.x * 32, k0 = blockIdx.y * 32;
    int tx = threadIdx.x, ty = threadIdx.y;
    #pragma unroll
    for (int r = 0; r < 4; r++)
        t[ty + 8 * r][tx] = W[(size_t)(n0 + ty + 8 * r) * Kc + k0 + tx];
    __syncthreads();
    #pragma unroll
    for (int r = 0; r < 4; r++) {
        float v  = t[tx][ty + 8 * r];
        float hi = tf32_rna(v);
        size_t o = (size_t)(k0 + ty + 8 * r) * Nr + n0 + tx;
        WhT[o] = hi;
        WlT[o] = tf32_rna(v - hi);
    }
}

// aggregation on x, output k-major (no transpose needed): YT[c][m]
__global__ void agg_x_T(const float* __restrict__ x, const float* __restrict__ S0,
                        float* __restrict__ YhT, float* __restrict__ YlT) {
    int c = blockIdx.y;
    int m = blockIdx.x * 256 + threadIdx.x;
    if (m >= Mrows) return;
    int b = m / HW;
    float db = dinv_of(b);
    size_t xi = (size_t)(b * Cc + c) * HW + (m - b * HW);
    float v = db * db * (S0[b * Cc + c] + x[xi]);
    if (b > 0)      v += db * dinv_of(b - 1) * x[xi - (size_t)Cc * HW];
    if (b < NB - 1) v += db * dinv_of(b + 1) * x[xi + (size_t)Cc * HW];
    float hi = tf32_rna(v);
    YhT[(size_t)c * MP + m] = hi;
    YlT[(size_t)c * MP + m] = tf32_rna(v - hi);
}

// per-(feature, sample) sums of H1T rows -> S1T[k][16]
__global__ void sum_h(const float* __restrict__ H1T, float* __restrict__ S1T) {
    int k = blockIdx.x;
    int w = threadIdx.x >> 5, lane = threadIdx.x & 31;
    const float* src = H1T + (size_t)k * MP + w * HW;
    float s = 0.f;
    #pragma unroll 8
    for (int p = lane; p < HW; p += 32) s += src[p];
    #pragma unroll
    for (int off = 16; off; off >>= 1) s += __shfl_down_sync(0xffffffffu, s, off);
    if (lane == 0) S1T[k * 16 + w] = s;
}

// max over samples: out[o*961+p] = max_b H2T[o][b*961+p]
__global__ void max_k(const float* __restrict__ H2T, float* __restrict__ out) {
    int idx = blockIdx.x * 256 + threadIdx.x;
    if (idx >= OUTF * HW) return;
    int o = idx / HW, p = idx - o * HW;
    const float* src = H2T + (size_t)o * MP + p;
    float m = -INFINITY;
    #pragma unroll
    for (int b = 0; b < NB; b++) m = fmaxf(m, src[b * HW]);
    out[idx] = m;
}

// ---------------- tf32 mma.sync GEMM (3xTF32), 128x128 tile, cp.async DB -----
// C^T[n][m] = lrelu( sum_k A[m][k]*B[n][k] + bias[n] ), A/B given k-major.
// AGG: A built on the fly from H1T (k-major) + S1T per-sample sums.
template<int KTOT, int NTOT, bool AGG>
__global__ __launch_bounds__(256)
void gemm_mma(const float* __restrict__ AhT, const float* __restrict__ AlT,
              const float* __restrict__ H1T, const float* __restrict__ S1T,
              const float* __restrict__ BhT, const float* __restrict__ BlT,
              const float* __restrict__ bias, float* __restrict__ CT) {
    extern __shared__ float smf[];
    constexpr int ROW  = 136;              // padded floats per k-row
    constexpr int TILE = 32 * ROW;         // one 32k x 128 tile
    constexpr int BUF  = 4 * TILE;         // Ahi, Alo, Bhi, Blo
    constexpr int NC   = KTOT / 32;

    const int tid  = threadIdx.x;
    const int lane = tid & 31;
    const int wid  = tid >> 5;
    const int bm   = blockIdx.y * 128;
    const int bn   = blockIdx.x * 128;
    const int wm   = (wid & 1) * 64;
    const int wn   = (wid >> 1) * 32;
    const int g    = lane >> 2, tg = lane & 3;
    const uint32_t sb = smem_u32(smf);

    float acc[4][4][4];
    #pragma unroll
    for (int i = 0; i < 4; i++)
        #pragma unroll
        for (int j = 0; j < 4; j++)
            #pragma unroll
            for (int e = 0; e < 4; e++) acc[i][j][e] = 0.f;

    auto load_chunk = [&](int ch) {
        const int st = ch & 1;
        const int k0 = ch * 32;
        const uint32_t bufb = sb + st * BUF * 4;
        // ---- B tiles (hi, lo) via cp.async ----
        #pragma unroll
        for (int i = 0; i < 8; i++) {
            int q   = tid + i * 256;       // 0..2047
            int t   = q >> 10;             // 0:Bhi 1:Blo
            int rem = q & 1023;
            int row = rem >> 5, c16 = rem & 31;
            const float* src = (t ? BlT : BhT) + (size_t)(k0 + row) * NTOT + bn + c16 * 4;
            uint32_t dst = bufb + (uint32_t)((2 + t) * TILE + row * ROW + c16 * 4) * 4;
            CP_ASYNC16(dst, src);
        }
        if (!AGG) {
            // ---- A tiles via cp.async ----
            #pragma unroll
            for (int i = 0; i < 8; i++) {
                int q   = tid + i * 256;
                int t   = q >> 10;
                int rem = q & 1023;
                int row = rem >> 5, c16 = rem & 31;
                const float* src = (t ? AlT : AhT) + (size_t)(k0 + row) * MP + bm + c16 * 4;
                uint32_t dst = bufb + (uint32_t)(t * TILE + row * ROW + c16 * 4) * 4;
                CP_ASYNC16(dst, src);
            }
        } else {
            // ---- A tiles computed: agg(H1) with tf32 split ----
            float* bh = smf + st * BUF;
            #pragma unroll
            for (int i = 0; i < 4; i++) {
                int q   = tid + i * 256;   // 0..1023
                int row = q >> 5, qd = q & 31;
                int k = k0 + row;
                int m = bm + qd * 4;
                const float* hp = H1T + (size_t)k * MP + m;
                float vv[4];
                int b0 = m / HW; if (b0 > 7) b0 = 7;
                int b3 = (m + 3) / HW; if (b3 > 7) b3 = 7;
                if (b0 == b3) {
                    int b = b0;
                    float db = dinv_of(b);
                    float c0 = db * db;
                    float cm = (b > 0)      ? db * dinv_of(b - 1) : 0.f;
                    float cp = (b < NB - 1) ? db * dinv_of(b + 1) : 0.f;
                    float s = __ldg(&S1T[k * 16 + b]);
                    float4 h = *(const float4*)hp;
                    #pragma unroll
                    for (int e = 0; e < 4; e++) {
                        float v = c0 * (s + ((const float*)&h)[e]);
                        if (b > 0)      v += cm * __ldg(hp + e - HW);
                        if (b < NB - 1) v += cp * __ldg(hp + e + HW);
                        vv[e] = v;
                    }
                } else {
                    #pragma unroll
                    for (int e = 0; e < 4; e++) {
                        int mm = m + e;
                        int b = mm / HW; if (b > 7) b = 7;
                        float db = dinv_of(b);
                        float v = db * db * (__ldg(&S1T[k * 16 + b]) + __ldg(hp + e));
                        if (b > 0)      v += db * dinv_of(b - 1) * __ldg(hp + e - HW);
                        if (b < NB - 1) v += db * dinv_of(b + 1) * __ldg(hp + e + HW);
                        vv[e] = v;
                    }
                }
                float4 hi4, lo4;
                hi4.x = tf32_rna(vv[0]); lo4.x = tf32_rna(vv[0] - hi4.x);
                hi4.y = tf32_rna(vv[1]); lo4.y = tf32_rna(vv[1] - hi4.y);
                hi4.z = tf32_rna(vv[2]); lo4.z = tf32_rna(vv[2] - hi4.z);
                hi4.w = tf32_rna(vv[3]); lo4.w = tf32_rna(vv[3] - hi4.w);
                *(float4*)(bh + 0 * TILE + row * ROW + qd * 4) = hi4;
                *(float4*)(bh + 1 * TILE + row * ROW + qd * 4) = lo4;
            }
        }
    };

    // prologue
    load_chunk(0);
    CP_COMMIT();

    for (int ch = 0; ch < NC; ch++) {
        if (ch + 1 < NC) load_chunk(ch + 1);
        CP_COMMIT();
        CP_WAIT1();
        __syncthreads();

        const float* buf = smf + (ch & 1) * BUF;
        const float* Ah = buf;
        const float* Al = buf + TILE;
        const float* Bh = buf + 2 * TILE;
        const float* Bl = buf + 3 * TILE;

        #pragma unroll
        for (int kk = 0; kk < 4; kk++) {
            const int k = kk * 8;
            uint32_t ah[4][4], al[4][4], bh[4][2], bl[4][2];
            #pragma unroll
            for (int mt = 0; mt < 4; mt++) {
                int mb = wm + mt * 16 + g;
                ah[mt][0] = __float_as_uint(Ah[(k + tg) * ROW + mb]);
                ah[mt][1] = __float_as_uint(Ah[(k + tg) * ROW + mb + 8]);
                ah[mt][2] = __float_as_uint(Ah[(k + tg + 4) * ROW + mb]);
                ah[mt][3] = __float_as_uint(Ah[(k + tg + 4) * ROW + mb + 8]);
                al[mt][0] = __float_as_uint(Al[(k + tg) * ROW + mb]);
                al[mt][1] = __float_as_uint(Al[(k + tg) * ROW + mb + 8]);
                al[mt][2] = __float_as_uint(Al[(k + tg + 4) * ROW + mb]);
                al[mt][3] = __float_as_uint(Al[(k + tg + 4) * ROW + mb + 8]);
            }
            #pragma unroll
            for (int nt = 0; nt < 4; nt++) {
                int nb = wn + nt * 8 + g;
                bh[nt][0] = __float_as_uint(Bh[(k + tg) * ROW + nb]);
                bh[nt][1] = __float_as_uint(Bh[(k + tg + 4) * ROW + nb]);
                bl[nt][0] = __float_as_uint(Bl[(k + tg) * ROW + nb]);
                bl[nt][1] = __float_as_uint(Bl[(k + tg + 4) * ROW + nb]);
            }
            #pragma unroll
            for (int mt = 0; mt < 4; mt++)
                #pragma unroll
                for (int nt = 0; nt < 4; nt++) {
                    MMA_TF32(acc[mt][nt], ah[mt], bh[nt]);
                    MMA_TF32(acc[mt][nt], al[mt], bh[nt]);
                    MMA_TF32(acc[mt][nt], ah[mt], bl[nt]);
                }
        }
        __syncthreads();
    }

    // epilogue: bias + leaky relu, store transposed CT[n][m]
    #pragma unroll
    for (int mt = 0; mt < 4; mt++) {
        int m0 = bm + wm + mt * 16 + g;
        bool v0 = m0 < Mrows, v8 = (m0 + 8) < Mrows;
        #pragma unroll
        for (int nt = 0; nt < 4; nt++) {
            int n = bn + wn + nt * 8 + 2 * tg;
            float bb0 = __ldg(&bias[n]), bb1 = __ldg(&bias[n + 1]);
            float c0 = acc[mt][nt][0] + bb0;
            float c1 = acc[mt][nt][1] + bb1;
            float c2 = acc[mt][nt][2] + bb0;
            float c3 = acc[mt][nt][3] + bb1;
            c0 = c0 > 0.f ? c0 : 0.01f * c0;
            c1 = c1 > 0.f ? c1 : 0.01f * c1;
            c2 = c2 > 0.f ? c2 : 0.01f * c2;
            c3 = c3 > 0.f ? c3 : 0.01f * c3;
            if (v0) {
                CT[(size_t)n * MP + m0]       = c0;
                CT[(size_t)(n + 1) * MP + m0] = c1;
            }
            if (v8) {
                CT[(size_t)n * MP + m0 + 8]       = c2;
                CT[(size_t)(n + 1) * MP + m0 + 8] = c3;
            }
        }
    }
}

// ---------------- launcher ----------------------------------------------------
extern "C" void kernel_launch(void* const* d_in, const int* in_sizes, int n_in,
                              void* d_out, int out_size) {
    const float* x  = (const float*)d_in[0];
    const float* W1 = (const float*)d_in[1];
    const float* b1 = (const float*)d_in[2];
    const float* W2 = (const float*)d_in[3];
    const float* b2 = (const float*)d_in[4];
    float* out = (float*)d_out;

    float *S0, *YhT, *YlT, *W1h, *W1l, *W2h, *W2l, *H1T, *S1T, *H2T;
    cudaGetSymbolAddress((void**)&S0,  g_S0);
    cudaGetSymbolAddress((void**)&YhT, g_YhiT);
    cudaGetSymbolAddress((void**)&YlT, g_YloT);
    cudaGetSymbolAddress((void**)&W1h, g_W1hT);
    cudaGetSymbolAddress((void**)&W1l, g_W1lT);
    cudaGetSymbolAddress((void**)&W2h, g_W2hT);
    cudaGetSymbolAddress((void**)&W2l, g_W2lT);
    cudaGetSymbolAddress((void**)&H1T, g_H1T);
    cudaGetSymbolAddress((void**)&S1T, g_S1T);
    cudaGetSymbolAddress((void**)&H2T, g_H2T);

    constexpr int SMEM = 2 * 4 * (32 * 136) * 4;   // 139264 B
    cudaFuncSetAttribute(gemm_mma<Cc,  HID,  false>,
                         cudaFuncAttributeMaxDynamicSharedMemorySize, SMEM);
    cudaFuncSetAttribute(gemm_mma<HID, OUTF, true>,
                         cudaFuncAttributeMaxDynamicSharedMemorySize, SMEM);

    // 1) per-sample channel sums of x; weight transpose+split
    sum_x_kernel<<<NB * Cc, 256>>>(x, S0);
    wsplit_t<<<dim3(HID / 32, Cc / 32), dim3(32, 8)>>>(W1, W1h, W1l, HID, Cc);
    wsplit_t<<<dim3(OUTF / 32, HID / 32), dim3(32, 8)>>>(W2, W2h, W2l, OUTF, HID);

    // 2) aggregation on x -> YT (k-major), tf32 split
    agg_x_T<<<dim3((Mrows + 255) / 256, Cc), 256>>>(x, S0, YhT, YlT);

    // 3) GEMM1: H1T = lrelu(Y @ W1^T + b1)^T
    gemm_mma<Cc, HID, false><<<dim3(HID / 128, MP / 128), 256, SMEM>>>(
        YhT, YlT, nullptr, nullptr, W1h, W1l, b1, H1T);

    // 4) per-sample sums of H1
    sum_h<<<HID, 256>>>(H1T, S1T);

    // 5) GEMM2 (fused aggregation): H2T = lrelu(agg(H1) @ W2^T + b2)^T
    gemm_mma<HID, OUTF, true><<<dim3(OUTF / 128, MP / 128), 256, SMEM>>>(
        nullptr, nullptr, H1T, S1T, W2h, W2l, b2, H2T);

    // 6) max over samples
    max_k<<<(OUTF * HW + 255) / 256, 256>>>(H2T, out);
}

// round 4
// speedup vs baseline: 2.0239x; 2.0239x over previous
#include <cuda_runtime.h>
#include <cuda_bf16.h>
#include <math.h>
#include <cstdint>

// ---------------- problem constants ----------------------------------------
#define NB    8
#define Cc    256
#define HW    961
#define Mrows 7688
#define MP    7808          // padded M = 61*128
#define HID   512
#define OUTF  256

// ---------------- scratch (device globals; zero-initialized) ----------------
__device__ float    g_S0  [NB * Cc];
__device__ uint32_t g_YhP [(Cc / 2) * MP];     // packed bf16x2 (k even|odd) hi
__device__ uint32_t g_YlP [(Cc / 2) * MP];     // lo
__device__ uint32_t g_W1hP[(Cc / 2) * HID];
__device__ uint32_t g_W1lP[(Cc / 2) * HID];
__device__ uint32_t g_W2hP[(HID / 2) * OUTF];
__device__ uint32_t g_W2lP[(HID / 2) * OUTF];
__device__ float    g_H1T [HID * MP];
__device__ float    g_S1T [HID * 16];
__device__ float    g_H2T [OUTF * MP];

// ---------------- helpers ----------------------------------------------------
__device__ __forceinline__ uint32_t smem_u32(const void* p) {
    uint32_t a;
    asm("{ .reg .u64 t; cvta.to.shared.u64 t, %1; cvt.u32.u64 %0, t; }"
        : "=r"(a) : "l"(p));
    return a;
}

__device__ __forceinline__ float dinv_of(int b) {
    int deg = (b == 0 || b == NB - 1) ? 963 : 964;
    return 1.0f / sqrtf((float)deg);
}

// pack two fp32 into one bf16x2 word: low16 = v0 (even k), high16 = v1 (odd k)
__device__ __forceinline__ void bf16_split_pack(float v0, float v1,
                                                uint32_t& whi, uint32_t& wlo) {
    __nv_bfloat16 h0 = __float2bfloat16_rn(v0);
    __nv_bfloat16 h1 = __float2bfloat16_rn(v1);
    __nv_bfloat16 l0 = __float2bfloat16_rn(v0 - __bfloat162float(h0));
    __nv_bfloat16 l1 = __float2bfloat16_rn(v1 - __bfloat162float(h1));
    __nv_bfloat162 ph; ph.x = h0; ph.y = h1;
    __nv_bfloat162 pl; pl.x = l0; pl.y = l1;
    whi = *(uint32_t*)&ph;
    wlo = *(uint32_t*)&pl;
}

#define MMA_BF16(d, a, b) \
    asm volatile("mma.sync.aligned.m16n8k16.row.col.f32.bf16.bf16.f32 " \
                 "{%0,%1,%2,%3},{%4,%5,%6,%7},{%8,%9},{%0,%1,%2,%3};" \
                 : "+f"((d)[0]), "+f"((d)[1]), "+f"((d)[2]), "+f"((d)[3]) \
                 : "r"((a)[0]), "r"((a)[1]), "r"((a)[2]), "r"((a)[3]), \
                   "r"((b)[0]), "r"((b)[1]))

#define CP_ASYNC16(dst32, src) \
    asm volatile("cp.async.cg.shared.global [%0], [%1], 16;" :: "r"(dst32), "l"(src))
#define CP_COMMIT()  asm volatile("cp.async.commit_group;" ::: "memory")
#define CP_WAIT1()   asm volatile("cp.async.wait_group 1;" ::: "memory")

// ---------------- small kernels ----------------------------------------------
__global__ void sum_x_kernel(const float* __restrict__ x, float* __restrict__ S0) {
    int bc = blockIdx.x;
    const float* src = x + (size_t)bc * HW;
    float s = 0.f;
    for (int p = threadIdx.x; p < HW; p += 256) s += src[p];
    __shared__ float red[8];
    #pragma unroll
    for (int off = 16; off; off >>= 1) s += __shfl_down_sync(0xffffffffu, s, off);
    if ((threadIdx.x & 31) == 0) red[threadIdx.x >> 5] = s;
    __syncthreads();
    if (threadIdx.x < 8) {
        s = red[threadIdx.x];
        #pragma unroll
        for (int off = 4; off; off >>= 1) s += __shfl_down_sync(0xffu, s, off);
        if (threadIdx.x == 0) S0[bc] = s;
    }
}

// W[Nr][Kc] row-major -> packed bf16x2 hi/lo [Kc/2][Nr]
__global__ void wsplit_p(const float* __restrict__ W,
                         uint32_t* __restrict__ WhP, uint32_t* __restrict__ WlP,
                         int Nr, int Kc) {
    __shared__ float t[32][33];
    int n0 = blockIdx.x * 32, k0 = blockIdx.y * 32;
    int tx = threadIdx.x, ty = threadIdx.y;
    #pragma unroll
    for (int r = 0; r < 4; r++)
        t[ty + 8 * r][tx] = W[(size_t)(n0 + ty + 8 * r) * Kc + k0 + tx];
    __syncthreads();
    #pragma unroll
    for (int r = 0; r < 2; r++) {
        int k2l = ty + 8 * r;                 // 0..15
        float v0 = t[tx][2 * k2l];
        float v1 = t[tx][2 * k2l + 1];
        uint32_t wh, wl;
        bf16_split_pack(v0, v1, wh, wl);
        size_t o = (size_t)(k0 / 2 + k2l) * Nr + n0 + tx;
        WhP[o] = wh;
        WlP[o] = wl;
    }
}

// aggregation on x -> packed bf16x2 hi/lo [Cc/2][MP]
__global__ void agg_x_p(const float* __restrict__ x, const float* __restrict__ S0,
                        uint32_t* __restrict__ YhP, uint32_t* __restrict__ YlP) {
    int c2 = blockIdx.y;                      // 0..127
    int m  = blockIdx.x * 256 + threadIdx.x;
    if (m >= Mrows) return;
    int b = m / HW, p = m - b * HW;
    float db = dinv_of(b);
    float c0 = db * db;
    float cm = (b > 0)      ? db * dinv_of(b - 1) : 0.f;
    float cp = (b < NB - 1) ? db * dinv_of(b + 1) : 0.f;
    float v[2];
    #pragma unroll
    for (int e = 0; e < 2; e++) {
        int c = 2 * c2 + e;
        size_t xi = (size_t)(b * Cc + c) * HW + p;
        float vv = c0 * (S0[b * Cc + c] + x[xi]);
        if (b > 0)      vv += cm * x[xi - (size_t)Cc * HW];
        if (b < NB - 1) vv += cp * x[xi + (size_t)Cc * HW];
        v[e] = vv;
    }
    uint32_t wh, wl;
    bf16_split_pack(v[0], v[1], wh, wl);
    YhP[(size_t)c2 * MP + m] = wh;
    YlP[(size_t)c2 * MP + m] = wl;
}

// per-(feature, sample) sums of H1T rows -> S1T[k][16]
__global__ void sum_h(const float* __restrict__ H1T, float* __restrict__ S1T) {
    int k = blockIdx.x;
    int w = threadIdx.x >> 5, lane = threadIdx.x & 31;
    const float* src = H1T + (size_t)k * MP + w * HW;
    float s = 0.f;
    #pragma unroll 8
    for (int p = lane; p < HW; p += 32) s += src[p];
    #pragma unroll
    for (int off = 16; off; off >>= 1) s += __shfl_down_sync(0xffffffffu, s, off);
    if (lane == 0) S1T[k * 16 + w] = s;
}

// max over samples
__global__ void max_k(const float* __restrict__ H2T, float* __restrict__ out) {
    int idx = blockIdx.x * 256 + threadIdx.x;
    if (idx >= OUTF * HW) return;
    int o = idx / HW, p = idx - o * HW;
    const float* src = H2T + (size_t)o * MP + p;
    float m = -INFINITY;
    #pragma unroll
    for (int b = 0; b < NB; b++) m = fmaxf(m, src[b * HW]);
    out[idx] = m;
}

// ---------------- bf16 3-split mma.sync GEMM, 128x128 tile, cp.async DB ------
// C^T[n][m] = lrelu( sum_k A[m][k]*B[n][k] + bias[n] )
// A/B given as packed bf16x2 hi/lo, layout [k/2][cols].
// AGG: A built on the fly from H1T (fp32 k-major) + S1T per-sample sums.
template<int KTOT, int NTOT, bool AGG>
__global__ __launch_bounds__(256, 2)
void gemm_mma(const uint32_t* __restrict__ AhP, const uint32_t* __restrict__ AlP,
              const float* __restrict__ H1T, const float* __restrict__ S1T,
              const uint32_t* __restrict__ BhP, const uint32_t* __restrict__ BlP,
              const float* __restrict__ bias, float* __restrict__ CT) {
    extern __shared__ uint32_t smu[];
    constexpr int ROW  = 132;              // padded words per k2-row
    constexpr int TILE = 16 * ROW;         // 16 k2-rows x 128 cols
    constexpr int BUF  = 4 * TILE;         // Ahi, Alo, Bhi, Blo
    constexpr int NC   = KTOT / 32;

    const int tid  = threadIdx.x;
    const int lane = tid & 31;
    const int wid  = tid >> 5;
    const int bm   = blockIdx.y * 128;
    const int bn   = blockIdx.x * 128;
    const int wm   = (wid & 1) * 64;
    const int wn   = (wid >> 1) * 32;
    const int g    = lane >> 2, tg = lane & 3;
    const uint32_t sb = smem_u32(smu);

    float acc[4][4][4];
    #pragma unroll
    for (int i = 0; i < 4; i++)
        #pragma unroll
        for (int j = 0; j < 4; j++)
            #pragma unroll
            for (int e = 0; e < 4; e++) acc[i][j][e] = 0.f;

    auto load_chunk = [&](int ch) {
        const int st   = ch & 1;
        const int k2_0 = ch * 16;
        const uint32_t bufb = sb + (uint32_t)(st * BUF) * 4;
        if (!AGG) {
            #pragma unroll
            for (int i = 0; i < 8; i++) {
                int q   = tid + i * 256;       // 0..2047
                int t   = q >> 9;              // 0:Ahi 1:Alo 2:Bhi 3:Blo
                int rem = q & 511;
                int row = rem >> 5, c = rem & 31;
                const uint32_t* src;
                if (t < 2)
                    src = (t ? AlP : AhP) + (size_t)(k2_0 + row) * MP + bm + c * 4;
                else
                    src = (t == 3 ? BlP : BhP) + (size_t)(k2_0 + row) * NTOT + bn + c * 4;
                uint32_t dst = bufb + (uint32_t)(t * TILE + row * ROW + c * 4) * 4;
                CP_ASYNC16(dst, src);
            }
        } else {
            // B tiles via cp.async
            #pragma unroll
            for (int i = 0; i < 4; i++) {
                int q   = tid + i * 256;       // 0..1023
                int t   = q >> 9;              // 0:Bhi 1:Blo
                int rem = q & 511;
                int row = rem >> 5, c = rem & 31;
                const uint32_t* src =
                    (t ? BlP : BhP) + (size_t)(k2_0 + row) * NTOT + bn + c * 4;
                uint32_t dst = bufb + (uint32_t)((2 + t) * TILE + row * ROW + c * 4) * 4;
                CP_ASYNC16(dst, src);
            }
            // A tiles computed: agg(H1) -> packed bf16x2 hi/lo
            uint32_t* bA = smu + st * BUF;
            const int k0 = ch * 32;
            #pragma unroll
            for (int i = 0; i < 8; i++) {
                int q   = tid + i * 256;       // 0..2047
                int k2l = q >> 7;              // 0..15
                int mi  = q & 127;
                int k   = k0 + 2 * k2l;
                int m   = bm + mi;
                int b = m / HW; if (b > NB - 1) b = NB - 1;
                float db = dinv_of(b);
                float c0 = db * db;
                float cm = (b > 0)      ? db * dinv_of(b - 1) : 0.f;
                float cp = (b < NB - 1) ? db * dinv_of(b + 1) : 0.f;
                const float* h0 = H1T + (size_t)k * MP + m;
                const float* h1 = h0 + MP;
                float v0 = c0 * (__ldg(&S1T[k * 16 + b]) + __ldg(h0));
                float v1 = c0 * (__ldg(&S1T[(k + 1) * 16 + b]) + __ldg(h1));
                if (b > 0) {
                    v0 += cm * __ldg(h0 - HW);
                    v1 += cm * __ldg(h1 - HW);
                }
                if (b < NB - 1) {
                    v0 += cp * __ldg(h0 + HW);
                    v1 += cp * __ldg(h1 + HW);
                }
                uint32_t wh, wl;
                bf16_split_pack(v0, v1, wh, wl);
                bA[0 * TILE + k2l * ROW + mi] = wh;
                bA[1 * TILE + k2l * ROW + mi] = wl;
            }
        }
    };

    // prologue
    load_chunk(0);
    CP_COMMIT();

    for (int ch = 0; ch < NC; ch++) {
        if (ch + 1 < NC) load_chunk(ch + 1);
        CP_COMMIT();
        CP_WAIT1();
        __syncthreads();

        const uint32_t* buf = smu + (ch & 1) * BUF;
        const uint32_t* Ah = buf;
        const uint32_t* Al = buf + TILE;
        const uint32_t* Bh = buf + 2 * TILE;
        const uint32_t* Bl = buf + 3 * TILE;

        #pragma unroll
        for (int kk = 0; kk < 2; kk++) {
            const int kb = kk * 8;
            uint32_t bh[4][2], bl[4][2];
            #pragma unroll
            for (int nt = 0; nt < 4; nt++) {
                int nb = wn + nt * 8 + g;
                bh[nt][0] = Bh[(kb + tg) * ROW + nb];
                bh[nt][1] = Bh[(kb + tg + 4) * ROW + nb];
                bl[nt][0] = Bl[(kb + tg) * ROW + nb];
                bl[nt][1] = Bl[(kb + tg + 4) * ROW + nb];
            }
            #pragma unroll
            for (int mt = 0; mt < 4; mt++) {
                int mb = wm + mt * 16 + g;
                uint32_t ah[4], al[4];
                ah[0] = Ah[(kb + tg) * ROW + mb];
                ah[1] = Ah[(kb + tg) * ROW + mb + 8];
                ah[2] = Ah[(kb + tg + 4) * ROW + mb];
                ah[3] = Ah[(kb + tg + 4) * ROW + mb + 8];
                al[0] = Al[(kb + tg) * ROW + mb];
                al[1] = Al[(kb + tg) * ROW + mb + 8];
                al[2] = Al[(kb + tg + 4) * ROW + mb];
                al[3] = Al[(kb + tg + 4) * ROW + mb + 8];
                #pragma unroll
                for (int nt = 0; nt < 4; nt++) {
                    MMA_BF16(acc[mt][nt], ah, bh[nt]);
                    MMA_BF16(acc[mt][nt], al, bh[nt]);
                    MMA_BF16(acc[mt][nt], ah, bl[nt]);
                }
            }
        }
        __syncthreads();
    }

    // epilogue: bias + leaky relu, store transposed CT[n][m]
    #pragma unroll
    for (int mt = 0; mt < 4; mt++) {
        int m0 = bm + wm + mt * 16 + g;
        bool v0 = m0 < Mrows, v8 = (m0 + 8) < Mrows;
        #pragma unroll
        for (int nt = 0; nt < 4; nt++) {
            int n = bn + wn + nt * 8 + 2 * tg;
            float bb0 = __ldg(&bias[n]), bb1 = __ldg(&bias[n + 1]);
            float c0 = acc[mt][nt][0] + bb0;
            float c1 = acc[mt][nt][1] + bb1;
            float c2 = acc[mt][nt][2] + bb0;
            float c3 = acc[mt][nt][3] + bb1;
            c0 = c0 > 0.f ? c0 : 0.01f * c0;
            c1 = c1 > 0.f ? c1 : 0.01f * c1;
            c2 = c2 > 0.f ? c2 : 0.01f * c2;
            c3 = c3 > 0.f ? c3 : 0.01f * c3;
            if (v0) {
                CT[(size_t)n * MP + m0]       = c0;
                CT[(size_t)(n + 1) * MP + m0] = c1;
            }
            if (v8) {
                CT[(size_t)n * MP + m0 + 8]       = c2;
                CT[(size_t)(n + 1) * MP + m0 + 8] = c3;
            }
        }
    }
}

// ---------------- launcher ----------------------------------------------------
extern "C" void kernel_launch(void* const* d_in, const int* in_sizes, int n_in,
                              void* d_out, int out_size) {
    const float* x  = (const float*)d_in[0];
    const float* W1 = (const float*)d_in[1];
    const float* b1 = (const float*)d_in[2];
    const float* W2 = (const float*)d_in[3];
    const float* b2 = (const float*)d_in[4];
    float* out = (float*)d_out;

    float *S0, *H1T, *S1T, *H2T;
    uint32_t *YhP, *YlP, *W1h, *W1l, *W2h, *W2l;
    cudaGetSymbolAddress((void**)&S0,  g_S0);
    cudaGetSymbolAddress((void**)&YhP, g_YhP);
    cudaGetSymbolAddress((void**)&YlP, g_YlP);
    cudaGetSymbolAddress((void**)&W1h, g_W1hP);
    cudaGetSymbolAddress((void**)&W1l, g_W1lP);
    cudaGetSymbolAddress((void**)&W2h, g_W2hP);
    cudaGetSymbolAddress((void**)&W2l, g_W2lP);
    cudaGetSymbolAddress((void**)&H1T, g_H1T);
    cudaGetSymbolAddress((void**)&S1T, g_S1T);
    cudaGetSymbolAddress((void**)&H2T, g_H2T);

    constexpr int SMEM = 2 * 4 * (16 * 132) * 4;   // 67584 B
    cudaFuncSetAttribute(gemm_mma<Cc,  HID,  false>,
                         cudaFuncAttributeMaxDynamicSharedMemorySize, SMEM);
    cudaFuncSetAttribute(gemm_mma<HID, OUTF, true>,
                         cudaFuncAttributeMaxDynamicSharedMemorySize, SMEM);

    // 1) per-sample channel sums of x; weight transpose+split (packed bf16x2)
    sum_x_kernel<<<NB * Cc, 256>>>(x, S0);
    wsplit_p<<<dim3(HID / 32, Cc / 32), dim3(32, 8)>>>(W1, W1h, W1l, HID, Cc);
    wsplit_p<<<dim3(OUTF / 32, HID / 32), dim3(32, 8)>>>(W2, W2h, W2l, OUTF, HID);

    // 2) aggregation on x -> packed Y
    agg_x_p<<<dim3((Mrows + 255) / 256, Cc / 2), 256>>>(x, S0, YhP, YlP);

    // 3) GEMM1: H1T = lrelu(Y @ W1^T + b1)^T
    gemm_mma<Cc, HID, false><<<dim3(HID / 128, MP / 128), 256, SMEM>>>(
        YhP, YlP, nullptr, nullptr, W1h, W1l, b1, H1T);

    // 4) per-sample sums of H1
    sum_h<<<HID, 256>>>(H1T, S1T);

    // 5) GEMM2 (fused aggregation): H2T = lrelu(agg(H1) @ W2^T + b2)^T
    gemm_mma<HID, OUTF, true><<<dim3(OUTF / 128, MP / 128), 256, SMEM>>>(
        nullptr, nullptr, H1T, S1T, W2h, W2l, b2, H2T);

    // 6) max over samples
    max_k<<<(OUTF * HW + 255) / 256, 256>>>(H2T, out);
}

// round 6
// speedup vs baseline: 2.7422x; 1.3549x over previous
#include <cuda_runtime.h>
#include <cuda_fp16.h>
#include <math.h>
#include <cstdint>

// ---------------- problem constants ----------------------------------------
#define NB    8
#define Cc    256
#define HW    961
#define Mrows 7688
#define MP    7808          // padded M = 61*128
#define HID   512
#define OUTF  256

// ---------------- scratch (device globals; zero-initialized) ----------------
__device__ float    g_S0  [NB * Cc];
__device__ uint32_t g_YP  [(Cc / 2) * MP];     // packed fp16x2 (k even|odd), single
__device__ uint32_t g_W1hP[(Cc / 2) * HID];    // weights hi
__device__ uint32_t g_W1lP[(Cc / 2) * HID];    // weights lo (residual)
__device__ uint32_t g_W2hP[(HID / 2) * OUTF];
__device__ uint32_t g_W2lP[(HID / 2) * OUTF];
__device__ float    g_H1T [HID * MP];
__device__ float    g_S1T [HID * 16];
__device__ float    g_H2T [OUTF * MP];

// ---------------- helpers ----------------------------------------------------
__device__ __forceinline__ uint32_t smem_u32(const void* p) {
    uint32_t a;
    asm("{ .reg .u64 t; cvta.to.shared.u64 t, %1; cvt.u32.u64 %0, t; }"
        : "=r"(a) : "l"(p));
    return a;
}

__device__ __forceinline__ float dinv_of(int b) {
    int deg = (b == 0 || b == NB - 1) ? 963 : 964;
    return 1.0f / sqrtf((float)deg);
}

__device__ __forceinline__ uint32_t f16x2_pack(float v0, float v1) {
    __half2 h = __floats2half2_rn(v0, v1);
    return *(uint32_t*)&h;
}

// split two fp32 into fp16 hi + fp16 residual, packed
__device__ __forceinline__ void f16_split_pack(float v0, float v1,
                                               uint32_t& whi, uint32_t& wlo) {
    __half h0 = __float2half_rn(v0);
    __half h1 = __float2half_rn(v1);
    __half l0 = __float2half_rn(v0 - __half2float(h0));
    __half l1 = __float2half_rn(v1 - __half2float(h1));
    __half2 ph; ph.x = h0; ph.y = h1;
    __half2 pl; pl.x = l0; pl.y = l1;
    whi = *(uint32_t*)&ph;
    wlo = *(uint32_t*)&pl;
}

#define MMA_F16(d, a, b) \
    asm volatile("mma.sync.aligned.m16n8k16.row.col.f32.f16.f16.f32 " \
                 "{%0,%1,%2,%3},{%4,%5,%6,%7},{%8,%9},{%0,%1,%2,%3};" \
                 : "+f"((d)[0]), "+f"((d)[1]), "+f"((d)[2]), "+f"((d)[3]) \
                 : "r"((a)[0]), "r"((a)[1]), "r"((a)[2]), "r"((a)[3]), \
                   "r"((b)[0]), "r"((b)[1]))

#define CP_ASYNC16(dst32, src) \
    asm volatile("cp.async.cg.shared.global [%0], [%1], 16;" :: "r"(dst32), "l"(src))
#define CP_COMMIT()  asm volatile("cp.async.commit_group;" ::: "memory")
#define CP_WAIT1()   asm volatile("cp.async.wait_group 1;" ::: "memory")

// ---------------- small kernels ----------------------------------------------
__global__ void sum_x_kernel(const float* __restrict__ x, float* __restrict__ S0) {
    int bc = blockIdx.x;
    const float* src = x + (size_t)bc * HW;
    float s = 0.f;
    for (int p = threadIdx.x; p < HW; p += 256) s += src[p];
    __shared__ float red[8];
    #pragma unroll
    for (int off = 16; off; off >>= 1) s += __shfl_down_sync(0xffffffffu, s, off);
    if ((threadIdx.x & 31) == 0) red[threadIdx.x >> 5] = s;
    __syncthreads();
    if (threadIdx.x < 8) {
        s = red[threadIdx.x];
        #pragma unroll
        for (int off = 4; off; off >>= 1) s += __shfl_down_sync(0xffu, s, off);
        if (threadIdx.x == 0) S0[bc] = s;
    }
}

// W[Nr][Kc] row-major -> packed fp16x2 hi/lo [Kc/2][Nr]
__global__ void wsplit_p(const float* __restrict__ W,
                         uint32_t* __restrict__ WhP, uint32_t* __restrict__ WlP,
                         int Nr, int Kc) {
    __shared__ float t[32][33];
    int n0 = blockIdx.x * 32, k0 = blockIdx.y * 32;
    int tx = threadIdx.x, ty = threadIdx.y;
    #pragma unroll
    for (int r = 0; r < 4; r++)
        t[ty + 8 * r][tx] = W[(size_t)(n0 + ty + 8 * r) * Kc + k0 + tx];
    __syncthreads();
    #pragma unroll
    for (int r = 0; r < 2; r++) {
        int k2l = ty + 8 * r;                 // 0..15
        uint32_t wh, wl;
        f16_split_pack(t[tx][2 * k2l], t[tx][2 * k2l + 1], wh, wl);
        size_t o = (size_t)(k0 / 2 + k2l) * Nr + n0 + tx;
        WhP[o] = wh;
        WlP[o] = wl;
    }
}

// aggregation on x -> packed single fp16x2 [Cc/2][MP]
__global__ void agg_x_f16(const float* __restrict__ x, const float* __restrict__ S0,
                          uint32_t* __restrict__ YP) {
    int c2 = blockIdx.y;                      // 0..127
    int m  = blockIdx.x * 256 + threadIdx.x;
    if (m >= Mrows) return;
    int b = m / HW, p = m - b * HW;
    float db = dinv_of(b);
    float c0 = db * db;
    float cm = (b > 0)      ? db * dinv_of(b - 1) : 0.f;
    float cp = (b < NB - 1) ? db * dinv_of(b + 1) : 0.f;
    float v[2];
    #pragma unroll
    for (int e = 0; e < 2; e++) {
        int c = 2 * c2 + e;
        size_t xi = (size_t)(b * Cc + c) * HW + p;
        float vv = c0 * (S0[b * Cc + c] + x[xi]);
        if (b > 0)      vv += cm * x[xi - (size_t)Cc * HW];
        if (b < NB - 1) vv += cp * x[xi + (size_t)Cc * HW];
        v[e] = vv;
    }
    YP[(size_t)c2 * MP + m] = f16x2_pack(v[0], v[1]);
}

// per-(feature, sample) sums of H1T rows -> S1T[k][16]
__global__ void sum_h(const float* __restrict__ H1T, float* __restrict__ S1T) {
    int k = blockIdx.x;
    int w = threadIdx.x >> 5, lane = threadIdx.x & 31;
    const float* src = H1T + (size_t)k * MP + w * HW;
    float s = 0.f;
    #pragma unroll 8
    for (int p = lane; p < HW; p += 32) s += src[p];
    #pragma unroll
    for (int off = 16; off; off >>= 1) s += __shfl_down_sync(0xffffffffu, s, off);
    if (lane == 0) S1T[k * 16 + w] = s;
}

// max over samples
__global__ void max_k(const float* __restrict__ H2T, float* __restrict__ out) {
    int idx = blockIdx.x * 256 + threadIdx.x;
    if (idx >= OUTF * HW) return;
    int o = idx / HW, p = idx - o * HW;
    const float* src = H2T + (size_t)o * MP + p;
    float m = -INFINITY;
    #pragma unroll
    for (int b = 0; b < NB; b++) m = fmaxf(m, src[b * HW]);
    out[idx] = m;
}

// ---------------- fp16 2-product mma.sync GEMM, 64x128 CTA tile --------------
// C^T[n][m] = lrelu( sum_k A[m][k]*W[n][k] + bias[n] )
// A single fp16x2 packed [k/2][m]; W split hi/lo fp16x2 packed [k/2][n].
// AGG: A built on the fly from H1T (fp32 k-major) + S1T per-sample sums.
template<int KTOT, int NTOT, bool AGG>
__global__ __launch_bounds__(256)
void gemm_mma(const uint32_t* __restrict__ AP,
              const float* __restrict__ H1T, const float* __restrict__ S1T,
              const uint32_t* __restrict__ BhP, const uint32_t* __restrict__ BlP,
              const float* __restrict__ bias, float* __restrict__ CT) {
    extern __shared__ uint32_t smu[];
    constexpr int AROW  = 68;              // words per k2-row (64 + pad)
    constexpr int BROW  = 132;             // words per k2-row (128 + pad)
    constexpr int ATILE = 16 * AROW;       // 1088
    constexpr int BTILE = 16 * BROW;       // 2112
    constexpr int BUFW  = ATILE + 2 * BTILE;  // 5312 words
    constexpr int NC    = KTOT / 32;

    const int tid  = threadIdx.x;
    const int lane = tid & 31;
    const int wid  = tid >> 5;
    const int bm   = blockIdx.y * 64;
    const int bn   = blockIdx.x * 128;
    const int wm   = (wid & 1) * 32;
    const int wn   = (wid >> 1) * 32;
    const int g    = lane >> 2, tg = lane & 3;
    const uint32_t sb = smem_u32(smu);

    float acc[2][4][4];
    #pragma unroll
    for (int i = 0; i < 2; i++)
        #pragma unroll
        for (int j = 0; j < 4; j++)
            #pragma unroll
            for (int e = 0; e < 4; e++) acc[i][j][e] = 0.f;

    auto load_chunk = [&](int ch) {
        const int st   = ch & 1;
        const int k2_0 = ch * 16;
        const uint32_t bufb = sb + (uint32_t)(st * BUFW) * 4;
        // B tiles (hi, lo) via cp.async
        #pragma unroll
        for (int i = 0; i < 4; i++) {
            int q   = tid + i * 256;       // 0..1023
            int t   = q >> 9;              // 0:Bhi 1:Blo
            int rem = q & 511;
            int row = rem >> 5, c = rem & 31;
            const uint32_t* src =
                (t ? BlP : BhP) + (size_t)(k2_0 + row) * NTOT + bn + c * 4;
            uint32_t dst = bufb + (uint32_t)(ATILE + t * BTILE + row * BROW + c * 4) * 4;
            CP_ASYNC16(dst, src);
        }
        if (!AGG) {
            // A tile via cp.async: 16 rows x 64 words = 1024 words, 1 op/thread
            int row = tid >> 4, c = tid & 15;
            const uint32_t* src = AP + (size_t)(k2_0 + row) * MP + bm + c * 4;
            uint32_t dst = bufb + (uint32_t)(row * AROW + c * 4) * 4;
            CP_ASYNC16(dst, src);
        } else {
            // A computed: agg(H1) -> single fp16x2
            uint32_t* bA = smu + st * BUFW;
            const int k0 = ch * 32;
            #pragma unroll
            for (int i = 0; i < 4; i++) {
                int q   = tid + i * 256;   // 0..1023
                int k2l = q >> 6;          // 0..15
                int mi  = q & 63;
                int k   = k0 + 2 * k2l;
                int m   = bm + mi;
                int b = m / HW; if (b > NB - 1) b = NB - 1;
                float db = dinv_of(b);
                float c0 = db * db;
                float cm = (b > 0)      ? db * dinv_of(b - 1) : 0.f;
                float cp = (b < NB - 1) ? db * dinv_of(b + 1) : 0.f;
                const float* h0 = H1T + (size_t)k * MP + m;
                const float* h1 = h0 + MP;
                float v0 = c0 * (__ldg(&S1T[k * 16 + b]) + __ldg(h0));
                float v1 = c0 * (__ldg(&S1T[(k + 1) * 16 + b]) + __ldg(h1));
                if (b > 0) {
                    v0 += cm * __ldg(h0 - HW);
                    v1 += cm * __ldg(h1 - HW);
                }
                if (b < NB - 1) {
                    v0 += cp * __ldg(h0 + HW);
                    v1 += cp * __ldg(h1 + HW);
                }
                bA[k2l * AROW + mi] = f16x2_pack(v0, v1);
            }
        }
    };

    // prologue
    load_chunk(0);
    CP_COMMIT();

    for (int ch = 0; ch < NC; ch++) {
        if (ch + 1 < NC) load_chunk(ch + 1);
        CP_COMMIT();
        CP_WAIT1();
        __syncthreads();

        const uint32_t* Ab = smu + (ch & 1) * BUFW;
        const uint32_t* Bh = Ab + ATILE;
        const uint32_t* Bl = Ab + ATILE + BTILE;

        #pragma unroll
        for (int kk = 0; kk < 2; kk++) {
            const int kb = kk * 8;
            uint32_t a[2][4], bh[4][2], bl[4][2];
            #pragma unroll
            for (int mt = 0; mt < 2; mt++) {
                int mb = wm + mt * 16 + g;
                a[mt][0] = Ab[(kb + tg) * AROW + mb];
                a[mt][1] = Ab[(kb + tg) * AROW + mb + 8];
                a[mt][2] = Ab[(kb + tg + 4) * AROW + mb];
                a[mt][3] = Ab[(kb + tg + 4) * AROW + mb + 8];
            }
            #pragma unroll
            for (int nt = 0; nt < 4; nt++) {
                int nb = wn + nt * 8 + g;
                bh[nt][0] = Bh[(kb + tg) * BROW + nb];
                bh[nt][1] = Bh[(kb + tg + 4) * BROW + nb];
                bl[nt][0] = Bl[(kb + tg) * BROW + nb];
                bl[nt][1] = Bl[(kb + tg + 4) * BROW + nb];
            }
            // pass 1: A * Whi  (acc reuse distance = 8 MMAs)
            #pragma unroll
            for (int mt = 0; mt < 2; mt++)
                #pragma unroll
                for (int nt = 0; nt < 4; nt++)
                    MMA_F16(acc[mt][nt], a[mt], bh[nt]);
            // pass 2: A * Wlo
            #pragma unroll
            for (int mt = 0; mt < 2; mt++)
                #pragma unroll
                for (int nt = 0; nt < 4; nt++)
                    MMA_F16(acc[mt][nt], a[mt], bl[nt]);
        }
        __syncthreads();
    }

    // epilogue: bias + leaky relu, store transposed CT[n][m]
    #pragma unroll
    for (int mt = 0; mt < 2; mt++) {
        int m0 = bm + wm + mt * 16 + g;
        bool v0 = m0 < Mrows, v8 = (m0 + 8) < Mrows;
        #pragma unroll
        for (int nt = 0; nt < 4; nt++) {
            int n = bn + wn + nt * 8 + 2 * tg;
            float bb0 = __ldg(&bias[n]), bb1 = __ldg(&bias[n + 1]);
            float c0 = acc[mt][nt][0] + bb0;
            float c1 = acc[mt][nt][1] + bb1;
            float c2 = acc[mt][nt][2] + bb0;
            float c3 = acc[mt][nt][3] + bb1;
            c0 = c0 > 0.f ? c0 : 0.01f * c0;
            c1 = c1 > 0.f ? c1 : 0.01f * c1;
            c2 = c2 > 0.f ? c2 : 0.01f * c2;
            c3 = c3 > 0.f ? c3 : 0.01f * c3;
            if (v0) {
                CT[(size_t)n * MP + m0]       = c0;
                CT[(size_t)(n + 1) * MP + m0] = c1;
            }
            if (v8) {
                CT[(size_t)n * MP + m0 + 8]       = c2;
                CT[(size_t)(n + 1) * MP + m0 + 8] = c3;
            }
        }
    }
}

// ---------------- launcher ----------------------------------------------------
extern "C" void kernel_launch(void* const* d_in, const int* in_sizes, int n_in,
                              void* d_out, int out_size) {
    const float* x  = (const float*)d_in[0];
    const float* W1 = (const float*)d_in[1];
    const float* b1 = (const float*)d_in[2];
    const float* W2 = (const float*)d_in[3];
    const float* b2 = (const float*)d_in[4];
    float* out = (float*)d_out;

    float *S0, *H1T, *S1T, *H2T;
    uint32_t *YP, *W1h, *W1l, *W2h, *W2l;
    cudaGetSymbolAddress((void**)&S0,  g_S0);
    cudaGetSymbolAddress((void**)&YP,  g_YP);
    cudaGetSymbolAddress((void**)&W1h, g_W1hP);
    cudaGetSymbolAddress((void**)&W1l, g_W1lP);
    cudaGetSymbolAddress((void**)&W2h, g_W2hP);
    cudaGetSymbolAddress((void**)&W2l, g_W2lP);
    cudaGetSymbolAddress((void**)&H1T, g_H1T);
    cudaGetSymbolAddress((void**)&S1T, g_S1T);
    cudaGetSymbolAddress((void**)&H2T, g_H2T);

    constexpr int SMEM = 2 * 5312 * 4;   // 42496 B
    cudaFuncSetAttribute(gemm_mma<Cc,  HID,  false>,
                         cudaFuncAttributeMaxDynamicSharedMemorySize, SMEM);
    cudaFuncSetAttribute(gemm_mma<HID, OUTF, true>,
                         cudaFuncAttributeMaxDynamicSharedMemorySize, SMEM);

    // 1) per-sample channel sums of x; weight transpose + fp16 hi/lo split
    sum_x_kernel<<<NB * Cc, 256>>>(x, S0);
    wsplit_p<<<dim3(HID / 32, Cc / 32), dim3(32, 8)>>>(W1, W1h, W1l, HID, Cc);
    wsplit_p<<<dim3(OUTF / 32, HID / 32), dim3(32, 8)>>>(W2, W2h, W2l, OUTF, HID);

    // 2) aggregation on x -> packed single-fp16 Y
    agg_x_f16<<<dim3((Mrows + 255) / 256, Cc / 2), 256>>>(x, S0, YP);

    // 3) GEMM1: H1T = lrelu(Y @ W1^T + b1)^T
    gemm_mma<Cc, HID, false><<<dim3(HID / 128, MP / 64), 256, SMEM>>>(
        YP, nullptr, nullptr, W1h, W1l, b1, H1T);

    // 4) per-sample sums of H1
    sum_h<<<HID, 256>>>(H1T, S1T);

    // 5) GEMM2 (fused aggregation): H2T = lrelu(agg(H1) @ W2^T + b2)^T
    gemm_mma<HID, OUTF, true><<<dim3(OUTF / 128, MP / 64), 256, SMEM>>>(
        nullptr, H1T, S1T, W2h, W2l, b2, H2T);

    // 6) max over samples
    max_k<<<(OUTF * HW + 255) / 256, 256>>>(H2T, out);
}